// round 12
// baseline (speedup 1.0000x reference)
#include <cuda_runtime.h>
#include <cuda_bf16.h>
#include <cstdint>

// Problem constants (TRIP log_prob): B=32768, M=8, D=256, R=32
#define MM 8
#define DD 256
#define RR 32
#define NN (RR * RR)          // 1024
#define MT 128                // batch rows per margin block
#define BTOT 32768

#define LOG_2PI_F 1.8378770664093453f

// ---------------- global scratch ----------------
// B fragments pre-permuted for mma.sync m16n8k16 (margins GEMM):
// uint4 index u = ((((mode*4+ni)*8 + g)*16 + kstep)*2 + half)*32 + lane
__device__ uint4 g_bf4[MM * 4 * 8 * 16 * 2 * 32];         // 4 MB
__device__ __nv_bfloat16 g_marg[(size_t)BTOT * MM * NN];  // 512 MB margins [b][mode][n]
__device__ float g_s[MM * NN];                            // per-mode core sums (f32)
__device__ float g_lognorm;

// ---------------- helpers ----------------
__device__ __forceinline__ float softplus_f(float x) {
    return (x > 20.0f) ? x : log1pf(expf(x));
}
__device__ __forceinline__ uint32_t bf2_bits(float a, float b) {
    __nv_bfloat162 h = __floats2bfloat162_rn(a, b);  // .x=a (low), .y=b (high)
    return *reinterpret_cast<uint32_t*>(&h);
}
__device__ __forceinline__ uint32_t smem_u32(const void* p) {
    uint32_t a;
    asm("{ .reg .u64 t; cvta.to.shared.u64 t, %1; cvt.u32.u64 %0, t; }" : "=r"(a) : "l"(p));
    return a;
}
__device__ __forceinline__ void ldsm4(uint32_t& r0, uint32_t& r1,
                                      uint32_t& r2, uint32_t& r3, uint32_t addr) {
    asm volatile("ldmatrix.sync.aligned.m8n8.x4.shared.b16 {%0,%1,%2,%3}, [%4];"
                 : "=r"(r0), "=r"(r1), "=r"(r2), "=r"(r3) : "r"(addr));
}
__device__ __forceinline__ void ldsm4_trans(uint32_t& r0, uint32_t& r1,
                                            uint32_t& r2, uint32_t& r3, uint32_t addr) {
    asm volatile("ldmatrix.sync.aligned.m8n8.x4.trans.shared.b16 {%0,%1,%2,%3}, [%4];"
                 : "=r"(r0), "=r"(r1), "=r"(r2), "=r"(r3) : "r"(addr));
}
__device__ __forceinline__ void mma_bf16(float* d, const uint32_t* a,
                                         uint32_t b0, uint32_t b1) {
    asm volatile(
        "mma.sync.aligned.m16n8k16.row.col.f32.bf16.bf16.f32 "
        "{%0,%1,%2,%3}, {%4,%5,%6,%7}, {%8,%9}, {%0,%1,%2,%3};"
        : "+f"(d[0]), "+f"(d[1]), "+f"(d[2]), "+f"(d[3])
        : "r"(a[0]), "r"(a[1]), "r"(a[2]), "r"(a[3]), "r"(b0), "r"(b1));
}
__device__ __forceinline__ void cp_async16(uint32_t smem_addr, const void* gptr) {
    asm volatile("cp.async.cg.shared.global [%0], [%1], 16;"
                 :: "r"(smem_addr), "l"(gptr) : "memory");
}
__device__ __forceinline__ void cp_commit() {
    asm volatile("cp.async.commit_group;" ::: "memory");
}
template <int N>
__device__ __forceinline__ void cp_wait() {
    asm volatile("cp.async.wait_group %0;" :: "n"(N) : "memory");
}
// swizzled smem address: rows of 512B (256 bf16), 16B chunk XOR (row&7)
__device__ __forceinline__ uint32_t swz(uint32_t base, int row, int chunk) {
    return base + row * 512 + (((chunk) ^ (row & 7)) << 4);
}
// 4x4 transpose among quad lanes (regs v[0..3]); verified mapping:
// after: lane (4r+j) holds {lane 4r+i}.v[j] at position i.
__device__ __forceinline__ void quad_transpose(uint32_t v[4], int lane) {
    const int q = lane & 3;
    uint32_t t;
    t = __shfl_xor_sync(0xffffffffu, (q & 1) ? v[0] : v[1], 1);
    if (q & 1) v[0] = t; else v[1] = t;
    t = __shfl_xor_sync(0xffffffffu, (q & 1) ? v[2] : v[3], 1);
    if (q & 1) v[2] = t; else v[3] = t;
    t = __shfl_xor_sync(0xffffffffu, (q & 2) ? v[0] : v[2], 2);
    if (q & 2) v[0] = t; else v[2] = t;
    t = __shfl_xor_sync(0xffffffffu, (q & 2) ? v[1] : v[3], 2);
    if (q & 2) v[1] = t; else v[3] = t;
}

// ---------------- kernel: prep  softplus(cores) -> B fragments ----------------
__global__ void k_prep(const float* __restrict__ cores) {
    int u = blockIdx.x * blockDim.x + threadIdx.x;  // 262144
    int lane = u & 31;
    int half = (u >> 5) & 1;
    int ks = (u >> 6) & 15;
    int g = (u >> 10) & 7;
    int ni = (u >> 13) & 3;
    int mode = u >> 15;
    int ncol = lane >> 2, tig = lane & 3;

    uint4 out;
    uint32_t comp[4];
    #pragma unroll
    for (int c32 = 0; c32 < 4; ++c32) {
        int ntile = half * 2 + (c32 >> 1);
        int isb1 = c32 & 1;
        int n = g * 128 + ni * 32 + ntile * 8 + ncol;
        int d = ks * 16 + isb1 * 8 + tig * 2;
        size_t base = (size_t)mode * (DD * NN) + (size_t)d * NN + n;
        float x0 = __ldg(&cores[base]);
        float x1 = __ldg(&cores[base + NN]);   // d+1
        comp[c32] = bf2_bits(softplus_f(x0), softplus_f(x1));
    }
    out.x = comp[0]; out.y = comp[1]; out.z = comp[2]; out.w = comp[3];
    g_bf4[u] = out;
}

// ---------------- kernel: per-mode core sums (f32, straight from cores) ----------------
__global__ void k_modesum(const float* __restrict__ cores) {  // grid = MM, 1024 thr
    int mode = blockIdx.x;
    int t = threadIdx.x;  // n = 32j + c
    float a = 0.0f;
    const float* base = cores + (size_t)mode * (DD * NN) + t;
    #pragma unroll 4
    for (int d = 0; d < DD; ++d) a += softplus_f(base[(size_t)d * NN]);
    g_s[mode * NN + t] = a;
}

// ---------------- kernel: norm chain + log(trace) ----------------
__global__ void k_normchain() {  // 1 block, 1024 threads
    __shared__ float nrm[NN];
    __shared__ float s[NN];
    __shared__ float tmp[NN];
    int t = threadIdx.x;
    int r = t >> 5, c = t & 31;
    nrm[t] = g_s[t];
    __syncthreads();
    for (int i = 1; i < MM; ++i) {
        s[t] = g_s[i * NN + t];
        __syncthreads();
        float a = 0.0f;
        #pragma unroll
        for (int j = 0; j < RR; ++j) a += nrm[r * RR + j] * s[j * RR + c];
        tmp[t] = a;
        __syncthreads();
        nrm[t] = tmp[t];
        __syncthreads();
    }
    if (t == 0) {
        float tr = 0.0f;
        #pragma unroll
        for (int k = 0; k < RR; ++k) tr += nrm[k * (RR + 1)];
        g_lognorm = logf(tr);
    }
}

// ---------------- kernel: margins (HMMA m64xn32 warp tiles, B cp.async ring) ----------------
// grid = (B/128)*8, mode = bx>>8. SMEM: A = E[128][256] bf16 swizzled (64KB)
// + B ring: 8 stages x 8KB (stage = [nj(8)][half(2)][lane(32)] uint4).
#define SM_RING 65536
#define M_SMEM (65536 + 65536)

__global__ void __launch_bounds__(512, 1)
k_margins(const float* __restrict__ value,
          const float* __restrict__ location,
          const float* __restrict__ log_scale) {
    extern __shared__ unsigned char sm[];
    __shared__ float sloc[DD], sinv[DD], scb[DD];

    const uint32_t aA = smem_u32(sm);
    const uint32_t aR = aA + SM_RING;
    const int tid = threadIdx.x;
    const int wid = tid >> 5;
    const int lane = tid & 31;
    const int mode = blockIdx.x >> 8;
    const int bblk = (blockIdx.x & 255) * MT;

    // staging role for this thread: one uint4 per stage
    const int s_nj = tid >> 6;
    const int s_half = (tid >> 5) & 1;
    const int s_lane = tid & 31;
    const int s_njh = s_nj >> 2;
    const uint4* __restrict__ sbase =
        g_bf4 + (size_t)((mode * 4 + (s_nj & 3)) * 8192) + s_half * 32 + s_lane;
    const uint32_t s_dst0 = aR + s_nj * 1024 + s_half * 512 + s_lane * 16;

    #define BOFF(t, njh) ((size_t)(((((t) >> 4) * 2 + (njh)) * 16 + ((t) & 15)) * 64))

    // ---- prologue: stage B for t = 0..5 (overlaps with exp phase) ----
    #pragma unroll
    for (int s = 0; s < 6; ++s) {
        cp_async16(s_dst0 + s * 8192, sbase + BOFF(s, s_njh));
        cp_commit();
    }

    if (tid < DD) {
        float lsi = __ldg(&log_scale[tid * MM + mode]);
        sloc[tid] = __ldg(&location[tid * MM + mode]);
        sinv[tid] = __expf(-lsi);
        scb[tid] = -0.5f * LOG_2PI_F - lsi;
    }
    __syncthreads();

    // ---- E tile: Gaussian weights bf16 into swizzled A smem ----
    {
        const int b = tid >> 2;     // batch row 0..127
        const int quad = tid & 3;   // d-range quad*64..+63
        const float v = __ldg(&value[(size_t)(bblk + b) * MM + mode]);
        #pragma unroll
        for (int dd = 0; dd < 64; dd += 2) {
            const int d = quad * 64 + dd;
            float z0 = (v - sloc[d]) * sinv[d];
            float p0 = __expf(fmaf(-0.5f * z0, z0, scb[d]));
            float z1 = (v - sloc[d + 1]) * sinv[d + 1];
            float p1 = __expf(fmaf(-0.5f * z1, z1, scb[d + 1]));
            uint32_t addr = swz(aA, b, d >> 3) + (d & 7) * 2;
            asm volatile("st.shared.b32 [%0], %1;" :: "r"(addr), "r"(bf2_bits(p0, p1)));
        }
    }
    __syncthreads();

    const int mi2 = wid & 1;
    const int nj = wid >> 1;       // 0..7
    const int a_row = mi2 * 64 + (lane & 7) + ((lane >> 3) & 1) * 8;
    const int a_cad = lane >> 4;
    const uint32_t b_rd = aR + nj * 1024 + lane * 16;  // + stage*8192 (+512 half1)

    for (int cg = 0; cg < 4; ++cg) {
        float acc[4][4][4];
        #pragma unroll
        for (int mt = 0; mt < 4; ++mt)
            #pragma unroll
            for (int nt = 0; nt < 4; ++nt)
                #pragma unroll
                for (int e = 0; e < 4; ++e) acc[mt][nt][e] = 0.0f;

        #pragma unroll 4
        for (int ks = 0; ks < 16; ++ks) {
            const int t = cg * 16 + ks;

            cp_wait<5>();        // stage t resident (groups complete in order)
            __syncthreads();     // cross-thread visibility; also guards ring reuse

            // issue stage t+6 into ring slot (t+6)&7 (read at iter t-2; safe)
            if (t + 6 < 64)
                cp_async16(s_dst0 + ((t + 6) & 7) * 8192, sbase + BOFF(t + 6, s_njh));
            cp_commit();         // uniform group count (empty groups ok)

            // B fragments from the ring (LDS.128 x2, warp-coalesced)
            const uint32_t st = b_rd + (t & 7) * 8192;
            uint4 P0, P1;
            asm volatile("ld.shared.v4.u32 {%0,%1,%2,%3}, [%4];"
                         : "=r"(P0.x), "=r"(P0.y), "=r"(P0.z), "=r"(P0.w) : "r"(st));
            asm volatile("ld.shared.v4.u32 {%0,%1,%2,%3}, [%4];"
                         : "=r"(P1.x), "=r"(P1.y), "=r"(P1.z), "=r"(P1.w) : "r"(st + 512));

            uint32_t a[4][4];
            #pragma unroll
            for (int mt = 0; mt < 4; ++mt)
                ldsm4(a[mt][0], a[mt][1], a[mt][2], a[mt][3],
                      swz(aA, a_row + mt * 16, 2 * ks + a_cad));

            #pragma unroll
            for (int mt = 0; mt < 4; ++mt) {
                mma_bf16(acc[mt][0], a[mt], P0.x, P0.y);
                mma_bf16(acc[mt][1], a[mt], P0.z, P0.w);
                mma_bf16(acc[mt][2], a[mt], P1.x, P1.y);
                mma_bf16(acc[mt][3], a[mt], P1.z, P1.w);
            }
        }

        // ---- store margins bf16: quad transpose -> coalesced STG.128 ----
        #pragma unroll
        for (int mt = 0; mt < 4; ++mt) {
            uint32_t lo[4], hi[4];
            #pragma unroll
            for (int nt = 0; nt < 4; ++nt) {
                lo[nt] = bf2_bits(acc[mt][nt][0], acc[mt][nt][1]);
                hi[nt] = bf2_bits(acc[mt][nt][2], acc[mt][nt][3]);
            }
            quad_transpose(lo, lane);
            quad_transpose(hi, lane);
            const int row = bblk + mi2 * 64 + mt * 16 + (lane >> 2);
            const int col = cg * 256 + nj * 32 + (lane & 3) * 8;
            *reinterpret_cast<uint4*>(
                &g_marg[((size_t)row * MM + mode) * NN + col]) =
                make_uint4(lo[0], lo[1], lo[2], lo[3]);
            *reinterpret_cast<uint4*>(
                &g_marg[((size_t)(row + 8) * MM + mode) * NN + col]) =
                make_uint4(hi[0], hi[1], hi[2], hi[3]);
        }
    }
    #undef BOFF
}

// ---------------- kernel: chain via HMMA, state in D-fragments ----------------
// One warp = one batch; 16 warps/block; grid = B/16 = 2048.
#define CH_BUF 2560
#define C_SMEM (16 * 2 * CH_BUF)   // 81920

__global__ void __launch_bounds__(512, 2)
k_chain(float* __restrict__ out) {
    extern __shared__ unsigned char sm[];
    const int tid = threadIdx.x;
    const int wid = tid >> 5;
    const int lane = tid & 31;
    const int b = blockIdx.x * 16 + wid;

    unsigned char* buf = sm + wid * (2 * CH_BUF);
    const uint32_t abuf = smem_u32(buf);
    const char* gsrc = (const char*)(g_marg + (size_t)b * MM * NN);

    #pragma unroll
    for (int k = 0; k < 4; ++k) {
        int q = lane + 32 * k;
        cp_async16(abuf + (q >> 2) * 80 + (q & 3) * 16, gsrc + q * 16);
    }
    cp_commit();
    #pragma unroll
    for (int k = 0; k < 4; ++k) {
        int q = lane + 32 * k;
        cp_async16(abuf + CH_BUF + (q >> 2) * 80 + (q & 3) * 16, gsrc + 2048 + q * 16);
    }
    cp_commit();

    cp_wait<1>();
    __syncwarp();

    float D[2][4][4];
    {
        const int r0 = lane >> 2, c0 = 2 * (lane & 3);
        #pragma unroll
        for (int mt = 0; mt < 2; ++mt)
            #pragma unroll
            for (int nt = 0; nt < 4; ++nt) {
                int r = 16 * mt + r0, c = 8 * nt + c0;
                __nv_bfloat162 v0 =
                    *reinterpret_cast<__nv_bfloat162*>(buf + r * 80 + c * 2);
                __nv_bfloat162 v1 =
                    *reinterpret_cast<__nv_bfloat162*>(buf + (r + 8) * 80 + c * 2);
                float2 f0 = __bfloat1622float2(v0);
                float2 f1 = __bfloat1622float2(v1);
                D[mt][nt][0] = f0.x; D[mt][nt][1] = f0.y;
                D[mt][nt][2] = f1.x; D[mt][nt][3] = f1.y;
            }
    }

    const int i8 = lane & 7, tsel = lane >> 3;

    for (int m = 1; m < MM; ++m) {
        if (m < MM - 1) {
            uint32_t dst = abuf + ((m + 1) & 1) * CH_BUF;
            const char* src = gsrc + (size_t)(m + 1) * 2048;
            #pragma unroll
            for (int k = 0; k < 4; ++k) {
                int q = lane + 32 * k;
                cp_async16(dst + (q >> 2) * 80 + (q & 3) * 16, src + q * 16);
            }
            cp_commit();
            cp_wait<1>();
        } else {
            cp_wait<0>();
        }
        __syncwarp();

        const uint32_t mb = abuf + (m & 1) * CH_BUF;

        uint32_t B[2][4][2];
        #pragma unroll
        for (int ks = 0; ks < 2; ++ks)
            #pragma unroll
            for (int nh = 0; nh < 2; ++nh) {
                uint32_t addr = mb + (16 * ks + (tsel & 1) * 8 + i8) * 80 +
                                32 * nh + (tsel >> 1) * 16;
                uint32_t q0, q1, q2, q3;
                ldsm4_trans(q0, q1, q2, q3, addr);
                B[ks][2 * nh][0] = q0;     B[ks][2 * nh][1] = q1;
                B[ks][2 * nh + 1][0] = q2; B[ks][2 * nh + 1][1] = q3;
            }

        uint32_t A[2][2][4];
        #pragma unroll
        for (int mt = 0; mt < 2; ++mt)
            #pragma unroll
            for (int ks = 0; ks < 2; ++ks) {
                A[mt][ks][0] = bf2_bits(D[mt][2 * ks][0], D[mt][2 * ks][1]);
                A[mt][ks][1] = bf2_bits(D[mt][2 * ks][2], D[mt][2 * ks][3]);
                A[mt][ks][2] = bf2_bits(D[mt][2 * ks + 1][0], D[mt][2 * ks + 1][1]);
                A[mt][ks][3] = bf2_bits(D[mt][2 * ks + 1][2], D[mt][2 * ks + 1][3]);
            }

        #pragma unroll
        for (int mt = 0; mt < 2; ++mt)
            #pragma unroll
            for (int nt = 0; nt < 4; ++nt)
                #pragma unroll
                for (int e = 0; e < 4; ++e) D[mt][nt][e] = 0.0f;

        #pragma unroll
        for (int mt = 0; mt < 2; ++mt)
            #pragma unroll
            for (int nt = 0; nt < 4; ++nt)
                #pragma unroll
                for (int ks = 0; ks < 2; ++ks)
                    mma_bf16(D[mt][nt], A[mt][ks], B[ks][nt][0], B[ks][nt][1]);
    }

    {
        float tr = 0.0f;
        const int r0 = lane >> 2, c0 = 2 * (lane & 3);
        #pragma unroll
        for (int mt = 0; mt < 2; ++mt)
            #pragma unroll
            for (int nt = 0; nt < 4; ++nt) {
                int rA = 16 * mt + r0, rB = rA + 8, c = 8 * nt + c0;
                if (c == rA)     tr += D[mt][nt][0];
                if (c + 1 == rA) tr += D[mt][nt][1];
                if (c == rB)     tr += D[mt][nt][2];
                if (c + 1 == rB) tr += D[mt][nt][3];
            }
        #pragma unroll
        for (int o = 16; o > 0; o >>= 1) tr += __shfl_xor_sync(0xffffffffu, tr, o);
        if (lane == 0)
            out[b] = logf(fmaxf(tr, 1e-12f)) - g_lognorm;
    }
}

// ---------------- launch ----------------
extern "C" void kernel_launch(void* const* d_in, const int* in_sizes, int n_in,
                              void* d_out, int out_size) {
    const float* value     = (const float*)d_in[0];  // (B, M)
    const float* location  = (const float*)d_in[1];  // (D, M)
    const float* log_scale = (const float*)d_in[2];  // (D, M)
    const float* cores     = (const float*)d_in[3];  // (M, D, R, R)
    float* out = (float*)d_out;

    const int B = in_sizes[0] / MM;   // 32768

    k_prep<<<(MM * 4 * 8 * 16 * 2 * 32) / 256, 256>>>(cores);
    k_modesum<<<MM, 1024>>>(cores);
    k_normchain<<<1, 1024>>>();

    static bool attr_done = false;
    if (!attr_done) {
        cudaFuncSetAttribute(k_margins,
                             cudaFuncAttributeMaxDynamicSharedMemorySize, M_SMEM);
        cudaFuncSetAttribute(k_chain,
                             cudaFuncAttributeMaxDynamicSharedMemorySize, C_SMEM);
        attr_done = true;
    }

    k_margins<<<(B / MT) * MM, 512, M_SMEM>>>(value, location, log_scale);
    k_chain<<<B / 16, 512, C_SMEM>>>(out);
}

// round 13
// speedup vs baseline: 1.1472x; 1.1472x over previous
#include <cuda_runtime.h>
#include <cuda_bf16.h>
#include <cstdint>

// Problem constants (TRIP log_prob): B=32768, M=8, D=256, R=32
#define MM 8
#define DD 256
#define RR 32
#define NN (RR * RR)          // 1024
#define MT 128                // batch rows per margin block
#define BTOT 32768

#define LOG_2PI_F 1.8378770664093453f

// ---------------- global scratch ----------------
// B fragments pre-permuted for mma.sync m16n8k16 (margins GEMM):
// uint4 index u = ((((mode*4+ni)*8 + g)*16 + kstep)*2 + half)*32 + lane
__device__ uint4 g_bf4[MM * 4 * 8 * 16 * 2 * 32];         // 4 MB
__device__ __nv_bfloat16 g_marg[(size_t)BTOT * MM * NN];  // 512 MB margins [b][mode][n]
__device__ float g_s[MM * NN];                            // per-mode core sums (f32)
__device__ float g_lognorm;

// ---------------- helpers ----------------
__device__ __forceinline__ float softplus_f(float x) {
    return (x > 20.0f) ? x : log1pf(expf(x));
}
__device__ __forceinline__ uint32_t bf2_bits(float a, float b) {
    __nv_bfloat162 h = __floats2bfloat162_rn(a, b);  // .x=a (low), .y=b (high)
    return *reinterpret_cast<uint32_t*>(&h);
}
__device__ __forceinline__ uint32_t smem_u32(const void* p) {
    uint32_t a;
    asm("{ .reg .u64 t; cvta.to.shared.u64 t, %1; cvt.u32.u64 %0, t; }" : "=r"(a) : "l"(p));
    return a;
}
__device__ __forceinline__ void ldsm4(uint32_t& r0, uint32_t& r1,
                                      uint32_t& r2, uint32_t& r3, uint32_t addr) {
    asm volatile("ldmatrix.sync.aligned.m8n8.x4.shared.b16 {%0,%1,%2,%3}, [%4];"
                 : "=r"(r0), "=r"(r1), "=r"(r2), "=r"(r3) : "r"(addr));
}
__device__ __forceinline__ void ldsm4_trans(uint32_t& r0, uint32_t& r1,
                                            uint32_t& r2, uint32_t& r3, uint32_t addr) {
    asm volatile("ldmatrix.sync.aligned.m8n8.x4.trans.shared.b16 {%0,%1,%2,%3}, [%4];"
                 : "=r"(r0), "=r"(r1), "=r"(r2), "=r"(r3) : "r"(addr));
}
__device__ __forceinline__ void mma_bf16(float* d, const uint32_t* a,
                                         uint32_t b0, uint32_t b1) {
    asm volatile(
        "mma.sync.aligned.m16n8k16.row.col.f32.bf16.bf16.f32 "
        "{%0,%1,%2,%3}, {%4,%5,%6,%7}, {%8,%9}, {%0,%1,%2,%3};"
        : "+f"(d[0]), "+f"(d[1]), "+f"(d[2]), "+f"(d[3])
        : "r"(a[0]), "r"(a[1]), "r"(a[2]), "r"(a[3]), "r"(b0), "r"(b1));
}
__device__ __forceinline__ void cp_async16(uint32_t smem_addr, const void* gptr) {
    asm volatile("cp.async.cg.shared.global [%0], [%1], 16;"
                 :: "r"(smem_addr), "l"(gptr) : "memory");
}
__device__ __forceinline__ void cp_commit() {
    asm volatile("cp.async.commit_group;" ::: "memory");
}
template <int N>
__device__ __forceinline__ void cp_wait() {
    asm volatile("cp.async.wait_group %0;" :: "n"(N) : "memory");
}
__device__ __forceinline__ void stg_cs_128(void* gptr, uint4 v) {
    asm volatile("st.global.cs.v4.u32 [%0], {%1,%2,%3,%4};"
                 :: "l"(gptr), "r"(v.x), "r"(v.y), "r"(v.z), "r"(v.w) : "memory");
}
// swizzled smem address: rows of 512B (256 bf16), 16B chunk XOR (row&7)
__device__ __forceinline__ uint32_t swz(uint32_t base, int row, int chunk) {
    return base + row * 512 + (((chunk) ^ (row & 7)) << 4);
}
// 4x4 transpose among quad lanes (regs v[0..3]):
// after: lane (4r+j) holds {lane 4r+i}.v[j] at position i.
__device__ __forceinline__ void quad_transpose(uint32_t v[4], int lane) {
    const int q = lane & 3;
    uint32_t t;
    t = __shfl_xor_sync(0xffffffffu, (q & 1) ? v[0] : v[1], 1);
    if (q & 1) v[0] = t; else v[1] = t;
    t = __shfl_xor_sync(0xffffffffu, (q & 1) ? v[2] : v[3], 1);
    if (q & 1) v[2] = t; else v[3] = t;
    t = __shfl_xor_sync(0xffffffffu, (q & 2) ? v[0] : v[2], 2);
    if (q & 2) v[0] = t; else v[2] = t;
    t = __shfl_xor_sync(0xffffffffu, (q & 2) ? v[1] : v[3], 2);
    if (q & 2) v[1] = t; else v[3] = t;
}

// ---------------- kernel: prep  softplus(cores) -> B fragments ----------------
__global__ void k_prep(const float* __restrict__ cores) {
    int u = blockIdx.x * blockDim.x + threadIdx.x;  // 262144
    int lane = u & 31;
    int half = (u >> 5) & 1;
    int ks = (u >> 6) & 15;
    int g = (u >> 10) & 7;
    int ni = (u >> 13) & 3;
    int mode = u >> 15;
    int ncol = lane >> 2, tig = lane & 3;

    uint4 out;
    uint32_t comp[4];
    #pragma unroll
    for (int c32 = 0; c32 < 4; ++c32) {
        int ntile = half * 2 + (c32 >> 1);
        int isb1 = c32 & 1;
        int n = g * 128 + ni * 32 + ntile * 8 + ncol;
        int d = ks * 16 + isb1 * 8 + tig * 2;
        size_t base = (size_t)mode * (DD * NN) + (size_t)d * NN + n;
        float x0 = __ldg(&cores[base]);
        float x1 = __ldg(&cores[base + NN]);   // d+1
        comp[c32] = bf2_bits(softplus_f(x0), softplus_f(x1));
    }
    out.x = comp[0]; out.y = comp[1]; out.z = comp[2]; out.w = comp[3];
    g_bf4[u] = out;
}

// ---------------- kernel: per-mode core sums (f32, straight from cores) ----------------
__global__ void k_modesum(const float* __restrict__ cores) {  // grid = MM, 1024 thr
    int mode = blockIdx.x;
    int t = threadIdx.x;  // n = 32j + c
    float a = 0.0f;
    const float* base = cores + (size_t)mode * (DD * NN) + t;
    #pragma unroll 4
    for (int d = 0; d < DD; ++d) a += softplus_f(base[(size_t)d * NN]);
    g_s[mode * NN + t] = a;
}

// ---------------- kernel: norm chain + log(trace) ----------------
__global__ void k_normchain() {  // 1 block, 1024 threads
    __shared__ float nrm[NN];
    __shared__ float s[NN];
    __shared__ float tmp[NN];
    int t = threadIdx.x;
    int r = t >> 5, c = t & 31;
    nrm[t] = g_s[t];
    __syncthreads();
    for (int i = 1; i < MM; ++i) {
        s[t] = g_s[i * NN + t];
        __syncthreads();
        float a = 0.0f;
        #pragma unroll
        for (int j = 0; j < RR; ++j) a += nrm[r * RR + j] * s[j * RR + c];
        tmp[t] = a;
        __syncthreads();
        nrm[t] = tmp[t];
        __syncthreads();
    }
    if (t == 0) {
        float tr = 0.0f;
        #pragma unroll
        for (int k = 0; k < RR; ++k) tr += nrm[k * (RR + 1)];
        g_lognorm = logf(tr);
    }
}

// ---------------- kernel: margins (HMMA m64xn32 warp tiles; R11 B-path) ----------------
// grid = (B/128)*8, mode = bx>>8. 16 warps = 2(m-half of 64 rows) x 8(n).
// B via pre-packed global fragments, distance-2 register prefetch. No mainloop barriers.
#define M_SMEM 65536

__global__ void __launch_bounds__(512, 1)
k_margins(const float* __restrict__ value,
          const float* __restrict__ location,
          const float* __restrict__ log_scale) {
    extern __shared__ unsigned char sm[];
    __shared__ float sloc[DD], sinv[DD], scb[DD];

    const uint32_t aA = smem_u32(sm);
    const int tid = threadIdx.x;
    const int wid = tid >> 5;
    const int lane = tid & 31;
    const int mode = blockIdx.x >> 8;
    const int bblk = (blockIdx.x & 255) * MT;

    if (tid < DD) {
        float lsi = __ldg(&log_scale[tid * MM + mode]);
        sloc[tid] = __ldg(&location[tid * MM + mode]);
        sinv[tid] = __expf(-lsi);
        scb[tid] = -0.5f * LOG_2PI_F - lsi;
    }
    __syncthreads();

    // ---- E tile: Gaussian weights bf16 into swizzled A smem ----
    {
        const int b = tid >> 2;     // batch row 0..127
        const int quad = tid & 3;   // d-range quad*64..+63
        const float v = __ldg(&value[(size_t)(bblk + b) * MM + mode]);
        #pragma unroll
        for (int dd = 0; dd < 64; dd += 2) {
            const int d = quad * 64 + dd;
            float z0 = (v - sloc[d]) * sinv[d];
            float p0 = __expf(fmaf(-0.5f * z0, z0, scb[d]));
            float z1 = (v - sloc[d + 1]) * sinv[d + 1];
            float p1 = __expf(fmaf(-0.5f * z1, z1, scb[d + 1]));
            uint32_t addr = swz(aA, b, d >> 3) + (d & 7) * 2;
            asm volatile("st.shared.b32 [%0], %1;" :: "r"(addr), "r"(bf2_bits(p0, p1)));
        }
    }
    __syncthreads();

    const int mi2 = wid & 1;
    const int nj = wid >> 1;       // 0..7
    const int njh = nj >> 2;
    const int a_row = mi2 * 64 + (lane & 7) + ((lane >> 3) & 1) * 8;
    const int a_cad = lane >> 4;

    const uint4* __restrict__ bbase =
        g_bf4 + (size_t)((mode * 4 + (nj & 3)) * 8192) + lane;

    #define BOFF(t) ((size_t)(((((t) >> 4) * 2 + njh) * 16 + ((t) & 15)) * 64))

    uint4 P0 = __ldg(bbase + BOFF(0)), P1 = __ldg(bbase + BOFF(0) + 32);
    uint4 Q0 = __ldg(bbase + BOFF(1)), Q1 = __ldg(bbase + BOFF(1) + 32);

    for (int cg = 0; cg < 4; ++cg) {
        float acc[4][4][4];
        #pragma unroll
        for (int mt = 0; mt < 4; ++mt)
            #pragma unroll
            for (int nt = 0; nt < 4; ++nt)
                #pragma unroll
                for (int e = 0; e < 4; ++e) acc[mt][nt][e] = 0.0f;

        #pragma unroll
        for (int ks = 0; ks < 16; ++ks) {
            int t = cg * 16 + ks + 2;
            t = (t > 63) ? 63 : t;
            uint4 R0 = __ldg(bbase + BOFF(t));
            uint4 R1 = __ldg(bbase + BOFF(t) + 32);

            uint32_t a[4][4];
            #pragma unroll
            for (int mt = 0; mt < 4; ++mt)
                ldsm4(a[mt][0], a[mt][1], a[mt][2], a[mt][3],
                      swz(aA, a_row + mt * 16, 2 * ks + a_cad));

            #pragma unroll
            for (int mt = 0; mt < 4; ++mt) {
                mma_bf16(acc[mt][0], a[mt], P0.x, P0.y);
                mma_bf16(acc[mt][1], a[mt], P0.z, P0.w);
                mma_bf16(acc[mt][2], a[mt], P1.x, P1.y);
                mma_bf16(acc[mt][3], a[mt], P1.z, P1.w);
            }
            P0 = Q0; P1 = Q1; Q0 = R0; Q1 = R1;
        }

        // ---- store margins bf16: quad transpose -> coalesced streaming STG.128 ----
        #pragma unroll
        for (int mt = 0; mt < 4; ++mt) {
            uint32_t lo[4], hi[4];
            #pragma unroll
            for (int nt = 0; nt < 4; ++nt) {
                lo[nt] = bf2_bits(acc[mt][nt][0], acc[mt][nt][1]);
                hi[nt] = bf2_bits(acc[mt][nt][2], acc[mt][nt][3]);
            }
            quad_transpose(lo, lane);
            quad_transpose(hi, lane);
            const int row = bblk + mi2 * 64 + mt * 16 + (lane >> 2);
            const int col = cg * 256 + nj * 32 + (lane & 3) * 8;
            stg_cs_128(&g_marg[((size_t)row * MM + mode) * NN + col],
                       make_uint4(lo[0], lo[1], lo[2], lo[3]));
            stg_cs_128(&g_marg[((size_t)(row + 8) * MM + mode) * NN + col],
                       make_uint4(hi[0], hi[1], hi[2], hi[3]));
        }
    }
    #undef BOFF
}

// ---------------- kernel: chain via HMMA, state in D-fragments ----------------
// One warp = one batch; 16 warps/block; grid = B/16 = 2048.
#define CH_BUF 2560
#define C_SMEM (16 * 2 * CH_BUF)   // 81920

__global__ void __launch_bounds__(512, 2)
k_chain(float* __restrict__ out) {
    extern __shared__ unsigned char sm[];
    const int tid = threadIdx.x;
    const int wid = tid >> 5;
    const int lane = tid & 31;
    const int b = blockIdx.x * 16 + wid;

    unsigned char* buf = sm + wid * (2 * CH_BUF);
    const uint32_t abuf = smem_u32(buf);
    const char* gsrc = (const char*)(g_marg + (size_t)b * MM * NN);

    #pragma unroll
    for (int k = 0; k < 4; ++k) {
        int q = lane + 32 * k;
        cp_async16(abuf + (q >> 2) * 80 + (q & 3) * 16, gsrc + q * 16);
    }
    cp_commit();
    #pragma unroll
    for (int k = 0; k < 4; ++k) {
        int q = lane + 32 * k;
        cp_async16(abuf + CH_BUF + (q >> 2) * 80 + (q & 3) * 16, gsrc + 2048 + q * 16);
    }
    cp_commit();

    cp_wait<1>();
    __syncwarp();

    float D[2][4][4];
    {
        const int r0 = lane >> 2, c0 = 2 * (lane & 3);
        #pragma unroll
        for (int mt = 0; mt < 2; ++mt)
            #pragma unroll
            for (int nt = 0; nt < 4; ++nt) {
                int r = 16 * mt + r0, c = 8 * nt + c0;
                __nv_bfloat162 v0 =
                    *reinterpret_cast<__nv_bfloat162*>(buf + r * 80 + c * 2);
                __nv_bfloat162 v1 =
                    *reinterpret_cast<__nv_bfloat162*>(buf + (r + 8) * 80 + c * 2);
                float2 f0 = __bfloat1622float2(v0);
                float2 f1 = __bfloat1622float2(v1);
                D[mt][nt][0] = f0.x; D[mt][nt][1] = f0.y;
                D[mt][nt][2] = f1.x; D[mt][nt][3] = f1.y;
            }
    }

    const int i8 = lane & 7, tsel = lane >> 3;

    for (int m = 1; m < MM; ++m) {
        if (m < MM - 1) {
            uint32_t dst = abuf + ((m + 1) & 1) * CH_BUF;
            const char* src = gsrc + (size_t)(m + 1) * 2048;
            #pragma unroll
            for (int k = 0; k < 4; ++k) {
                int q = lane + 32 * k;
                cp_async16(dst + (q >> 2) * 80 + (q & 3) * 16, src + q * 16);
            }
            cp_commit();
            cp_wait<1>();
        } else {
            cp_wait<0>();
        }
        __syncwarp();

        const uint32_t mb = abuf + (m & 1) * CH_BUF;

        uint32_t B[2][4][2];
        #pragma unroll
        for (int ks = 0; ks < 2; ++ks)
            #pragma unroll
            for (int nh = 0; nh < 2; ++nh) {
                uint32_t addr = mb + (16 * ks + (tsel & 1) * 8 + i8) * 80 +
                                32 * nh + (tsel >> 1) * 16;
                uint32_t q0, q1, q2, q3;
                ldsm4_trans(q0, q1, q2, q3, addr);
                B[ks][2 * nh][0] = q0;     B[ks][2 * nh][1] = q1;
                B[ks][2 * nh + 1][0] = q2; B[ks][2 * nh + 1][1] = q3;
            }

        uint32_t A[2][2][4];
        #pragma unroll
        for (int mt = 0; mt < 2; ++mt)
            #pragma unroll
            for (int ks = 0; ks < 2; ++ks) {
                A[mt][ks][0] = bf2_bits(D[mt][2 * ks][0], D[mt][2 * ks][1]);
                A[mt][ks][1] = bf2_bits(D[mt][2 * ks][2], D[mt][2 * ks][3]);
                A[mt][ks][2] = bf2_bits(D[mt][2 * ks + 1][0], D[mt][2 * ks + 1][1]);
                A[mt][ks][3] = bf2_bits(D[mt][2 * ks + 1][2], D[mt][2 * ks + 1][3]);
            }

        #pragma unroll
        for (int mt = 0; mt < 2; ++mt)
            #pragma unroll
            for (int nt = 0; nt < 4; ++nt)
                #pragma unroll
                for (int e = 0; e < 4; ++e) D[mt][nt][e] = 0.0f;

        #pragma unroll
        for (int mt = 0; mt < 2; ++mt)
            #pragma unroll
            for (int nt = 0; nt < 4; ++nt)
                #pragma unroll
                for (int ks = 0; ks < 2; ++ks)
                    mma_bf16(D[mt][nt], A[mt][ks], B[ks][nt][0], B[ks][nt][1]);
    }

    {
        float tr = 0.0f;
        const int r0 = lane >> 2, c0 = 2 * (lane & 3);
        #pragma unroll
        for (int mt = 0; mt < 2; ++mt)
            #pragma unroll
            for (int nt = 0; nt < 4; ++nt) {
                int rA = 16 * mt + r0, rB = rA + 8, c = 8 * nt + c0;
                if (c == rA)     tr += D[mt][nt][0];
                if (c + 1 == rA) tr += D[mt][nt][1];
                if (c == rB)     tr += D[mt][nt][2];
                if (c + 1 == rB) tr += D[mt][nt][3];
            }
        #pragma unroll
        for (int o = 16; o > 0; o >>= 1) tr += __shfl_xor_sync(0xffffffffu, tr, o);
        if (lane == 0)
            out[b] = logf(fmaxf(tr, 1e-12f)) - g_lognorm;
    }
}

// ---------------- launch ----------------
extern "C" void kernel_launch(void* const* d_in, const int* in_sizes, int n_in,
                              void* d_out, int out_size) {
    const float* value     = (const float*)d_in[0];  // (B, M)
    const float* location  = (const float*)d_in[1];  // (D, M)
    const float* log_scale = (const float*)d_in[2];  // (D, M)
    const float* cores     = (const float*)d_in[3];  // (M, D, R, R)
    float* out = (float*)d_out;

    const int B = in_sizes[0] / MM;   // 32768

    k_prep<<<(MM * 4 * 8 * 16 * 2 * 32) / 256, 256>>>(cores);
    k_modesum<<<MM, 1024>>>(cores);
    k_normchain<<<1, 1024>>>();

    static bool attr_done = false;
    if (!attr_done) {
        cudaFuncSetAttribute(k_margins,
                             cudaFuncAttributeMaxDynamicSharedMemorySize, M_SMEM);
        cudaFuncSetAttribute(k_chain,
                             cudaFuncAttributeMaxDynamicSharedMemorySize, C_SMEM);
        attr_done = true;
    }

    k_margins<<<(B / MT) * MM, 512, M_SMEM>>>(value, location, log_scale);
    k_chain<<<B / 16, 512, C_SMEM>>>(out);
}

// round 14
// speedup vs baseline: 1.2723x; 1.1091x over previous
#include <cuda_runtime.h>
#include <cuda_bf16.h>
#include <cstdint>

// Problem constants (TRIP log_prob): B=32768, M=8, D=256, R=32
#define MM 8
#define DD 256
#define RR 32
#define NN (RR * RR)          // 1024
#define MT 128                // batch rows per margin block
#define BTOT 32768

#define LOG_2PI_F 1.8378770664093453f

// ---------------- global scratch ----------------
// B fragments pre-permuted for mma.sync m16n8k16 (margins GEMM):
// uint4 index u = ((((mode*4+ni)*8 + g)*16 + kstep)*2 + half)*32 + lane
__device__ uint4 g_bf4[MM * 4 * 8 * 16 * 2 * 32];         // 4 MB
__device__ __nv_bfloat16 g_marg[(size_t)BTOT * MM * NN];  // 512 MB margins [b][mode][n]
__device__ float g_s[MM * NN];                            // per-mode core sums (f32)
__device__ float g_lognorm;

// ---------------- helpers ----------------
__device__ __forceinline__ float softplus_f(float x) {
    return (x > 20.0f) ? x : log1pf(expf(x));
}
__device__ __forceinline__ uint32_t bf2_bits(float a, float b) {
    __nv_bfloat162 h = __floats2bfloat162_rn(a, b);  // .x=a (low), .y=b (high)
    return *reinterpret_cast<uint32_t*>(&h);
}
__device__ __forceinline__ uint32_t smem_u32(const void* p) {
    uint32_t a;
    asm("{ .reg .u64 t; cvta.to.shared.u64 t, %1; cvt.u32.u64 %0, t; }" : "=r"(a) : "l"(p));
    return a;
}
__device__ __forceinline__ void ldsm4(uint32_t& r0, uint32_t& r1,
                                      uint32_t& r2, uint32_t& r3, uint32_t addr) {
    asm volatile("ldmatrix.sync.aligned.m8n8.x4.shared.b16 {%0,%1,%2,%3}, [%4];"
                 : "=r"(r0), "=r"(r1), "=r"(r2), "=r"(r3) : "r"(addr));
}
__device__ __forceinline__ void ldsm4_trans(uint32_t& r0, uint32_t& r1,
                                            uint32_t& r2, uint32_t& r3, uint32_t addr) {
    asm volatile("ldmatrix.sync.aligned.m8n8.x4.trans.shared.b16 {%0,%1,%2,%3}, [%4];"
                 : "=r"(r0), "=r"(r1), "=r"(r2), "=r"(r3) : "r"(addr));
}
__device__ __forceinline__ void mma_bf16(float* d, const uint32_t* a,
                                         uint32_t b0, uint32_t b1) {
    asm volatile(
        "mma.sync.aligned.m16n8k16.row.col.f32.bf16.bf16.f32 "
        "{%0,%1,%2,%3}, {%4,%5,%6,%7}, {%8,%9}, {%0,%1,%2,%3};"
        : "+f"(d[0]), "+f"(d[1]), "+f"(d[2]), "+f"(d[3])
        : "r"(a[0]), "r"(a[1]), "r"(a[2]), "r"(a[3]), "r"(b0), "r"(b1));
}
__device__ __forceinline__ void cp_async16(uint32_t smem_addr, const void* gptr) {
    asm volatile("cp.async.cg.shared.global [%0], [%1], 16;"
                 :: "r"(smem_addr), "l"(gptr) : "memory");
}
__device__ __forceinline__ void cp_commit() {
    asm volatile("cp.async.commit_group;" ::: "memory");
}
template <int N>
__device__ __forceinline__ void cp_wait() {
    asm volatile("cp.async.wait_group %0;" :: "n"(N) : "memory");
}
__device__ __forceinline__ void stg_cs_128(void* gptr, uint4 v) {
    asm volatile("st.global.cs.v4.u32 [%0], {%1,%2,%3,%4};"
                 :: "l"(gptr), "r"(v.x), "r"(v.y), "r"(v.z), "r"(v.w) : "memory");
}
// swizzled smem address: rows of 512B (256 bf16), 16B chunk XOR (row&7)
__device__ __forceinline__ uint32_t swz(uint32_t base, int row, int chunk) {
    return base + row * 512 + (((chunk) ^ (row & 7)) << 4);
}
// 4x4 transpose among quad lanes (regs v[0..3]):
// after: lane (4r+j) holds {lane 4r+i}.v[j] at position i.
__device__ __forceinline__ void quad_transpose(uint32_t v[4], int lane) {
    const int q = lane & 3;
    uint32_t t;
    t = __shfl_xor_sync(0xffffffffu, (q & 1) ? v[0] : v[1], 1);
    if (q & 1) v[0] = t; else v[1] = t;
    t = __shfl_xor_sync(0xffffffffu, (q & 1) ? v[2] : v[3], 1);
    if (q & 1) v[2] = t; else v[3] = t;
    t = __shfl_xor_sync(0xffffffffu, (q & 2) ? v[0] : v[2], 2);
    if (q & 2) v[0] = t; else v[2] = t;
    t = __shfl_xor_sync(0xffffffffu, (q & 2) ? v[1] : v[3], 2);
    if (q & 2) v[1] = t; else v[3] = t;
}

// ---------------- kernel: prep  softplus(cores) -> B fragments ----------------
__global__ void k_prep(const float* __restrict__ cores) {
    int u = blockIdx.x * blockDim.x + threadIdx.x;  // 262144
    int lane = u & 31;
    int half = (u >> 5) & 1;
    int ks = (u >> 6) & 15;
    int g = (u >> 10) & 7;
    int ni = (u >> 13) & 3;
    int mode = u >> 15;
    int ncol = lane >> 2, tig = lane & 3;

    uint4 out;
    uint32_t comp[4];
    #pragma unroll
    for (int c32 = 0; c32 < 4; ++c32) {
        int ntile = half * 2 + (c32 >> 1);
        int isb1 = c32 & 1;
        int n = g * 128 + ni * 32 + ntile * 8 + ncol;
        int d = ks * 16 + isb1 * 8 + tig * 2;
        size_t base = (size_t)mode * (DD * NN) + (size_t)d * NN + n;
        float x0 = __ldg(&cores[base]);
        float x1 = __ldg(&cores[base + NN]);   // d+1
        comp[c32] = bf2_bits(softplus_f(x0), softplus_f(x1));
    }
    out.x = comp[0]; out.y = comp[1]; out.z = comp[2]; out.w = comp[3];
    g_bf4[u] = out;
}

// ---------------- kernel: per-mode core sums (f32, straight from cores) ----------------
__global__ void k_modesum(const float* __restrict__ cores) {  // grid = MM, 1024 thr
    int mode = blockIdx.x;
    int t = threadIdx.x;  // n = 32j + c
    float a = 0.0f;
    const float* base = cores + (size_t)mode * (DD * NN) + t;
    #pragma unroll 4
    for (int d = 0; d < DD; ++d) a += softplus_f(base[(size_t)d * NN]);
    g_s[mode * NN + t] = a;
}

// ---------------- kernel: norm chain + log(trace) ----------------
__global__ void k_normchain() {  // 1 block, 1024 threads
    __shared__ float nrm[NN];
    __shared__ float s[NN];
    __shared__ float tmp[NN];
    int t = threadIdx.x;
    int r = t >> 5, c = t & 31;
    nrm[t] = g_s[t];
    __syncthreads();
    for (int i = 1; i < MM; ++i) {
        s[t] = g_s[i * NN + t];
        __syncthreads();
        float a = 0.0f;
        #pragma unroll
        for (int j = 0; j < RR; ++j) a += nrm[r * RR + j] * s[j * RR + c];
        tmp[t] = a;
        __syncthreads();
        nrm[t] = tmp[t];
        __syncthreads();
    }
    if (t == 0) {
        float tr = 0.0f;
        #pragma unroll
        for (int k = 0; k < RR; ++k) tr += nrm[k * (RR + 1)];
        g_lognorm = logf(tr);
    }
}

// ---------------- kernel: margins (HMMA m128xn32 warp tiles; 8 warps) ----------------
// grid = (B/128)*8, mode = bx>>8. Each warp covers ALL 128 m-rows x 32 n-cols,
// so B fragments are loaded once per (ks, nj) — half the B traffic of the 16-warp
// m64 layout. 256 threads, high-reg (launch_bounds 256,1).
#define M_SMEM 65536

__global__ void __launch_bounds__(256, 1)
k_margins(const float* __restrict__ value,
          const float* __restrict__ location,
          const float* __restrict__ log_scale) {
    extern __shared__ unsigned char sm[];
    __shared__ float sloc[DD], sinv[DD], scb[DD];

    const uint32_t aA = smem_u32(sm);
    const int tid = threadIdx.x;
    const int wid = tid >> 5;      // 0..7 = nj
    const int lane = tid & 31;
    const int mode = blockIdx.x >> 8;
    const int bblk = (blockIdx.x & 255) * MT;

    {
        // 256 threads == DD
        float lsi = __ldg(&log_scale[tid * MM + mode]);
        sloc[tid] = __ldg(&location[tid * MM + mode]);
        sinv[tid] = __expf(-lsi);
        scb[tid] = -0.5f * LOG_2PI_F - lsi;
    }
    __syncthreads();

    // ---- E tile: Gaussian weights bf16 into swizzled A smem (vector STS.128) ----
    {
        const int b = tid >> 1;      // batch row 0..127
        const int half = tid & 1;    // d-range half*128..+127
        const float v = __ldg(&value[(size_t)(bblk + b) * MM + mode]);
        #pragma unroll
        for (int c = 0; c < 16; ++c) {
            const int chunk = half * 16 + c;   // 16B chunk = 8 d's
            uint32_t pr[4];
            #pragma unroll
            for (int e = 0; e < 4; ++e) {
                const int d = chunk * 8 + e * 2;
                float z0 = (v - sloc[d]) * sinv[d];
                float p0 = __expf(fmaf(-0.5f * z0, z0, scb[d]));
                float z1 = (v - sloc[d + 1]) * sinv[d + 1];
                float p1 = __expf(fmaf(-0.5f * z1, z1, scb[d + 1]));
                pr[e] = bf2_bits(p0, p1);
            }
            asm volatile("st.shared.v4.u32 [%0], {%1,%2,%3,%4};"
                         :: "r"(swz(aA, b, chunk)),
                            "r"(pr[0]), "r"(pr[1]), "r"(pr[2]), "r"(pr[3]));
        }
    }
    __syncthreads();

    const int nj = wid;            // 0..7
    const int njh = nj >> 2;
    const int a_row = (lane & 7) + ((lane >> 3) & 1) * 8;
    const int a_cad = lane >> 4;

    const uint4* __restrict__ bbase =
        g_bf4 + (size_t)((mode * 4 + (nj & 3)) * 8192) + lane;

    #define BOFF(t) ((size_t)(((((t) >> 4) * 2 + njh) * 16 + ((t) & 15)) * 64))

    uint4 P0 = __ldg(bbase + BOFF(0)), P1 = __ldg(bbase + BOFF(0) + 32);
    uint4 Q0 = __ldg(bbase + BOFF(1)), Q1 = __ldg(bbase + BOFF(1) + 32);

    for (int cg = 0; cg < 4; ++cg) {
        float acc[8][4][4];
        #pragma unroll
        for (int mt = 0; mt < 8; ++mt)
            #pragma unroll
            for (int nt = 0; nt < 4; ++nt)
                #pragma unroll
                for (int e = 0; e < 4; ++e) acc[mt][nt][e] = 0.0f;

        #pragma unroll
        for (int ks = 0; ks < 16; ++ks) {
            int t = cg * 16 + ks + 2;
            t = (t > 63) ? 63 : t;
            uint4 R0 = __ldg(bbase + BOFF(t));
            uint4 R1 = __ldg(bbase + BOFF(t) + 32);

            // 8 m-tiles: LDSM + 4 HMMA each; independent chains hide LDSM latency
            #pragma unroll
            for (int mt = 0; mt < 8; ++mt) {
                uint32_t a[4];
                ldsm4(a[0], a[1], a[2], a[3],
                      swz(aA, a_row + mt * 16, 2 * ks + a_cad));
                mma_bf16(acc[mt][0], a, P0.x, P0.y);
                mma_bf16(acc[mt][1], a, P0.z, P0.w);
                mma_bf16(acc[mt][2], a, P1.x, P1.y);
                mma_bf16(acc[mt][3], a, P1.z, P1.w);
            }
            P0 = Q0; P1 = Q1; Q0 = R0; Q1 = R1;
        }

        // ---- store margins bf16: quad transpose -> coalesced streaming STG.128 ----
        #pragma unroll
        for (int mt = 0; mt < 8; ++mt) {
            uint32_t lo[4], hi[4];
            #pragma unroll
            for (int nt = 0; nt < 4; ++nt) {
                lo[nt] = bf2_bits(acc[mt][nt][0], acc[mt][nt][1]);
                hi[nt] = bf2_bits(acc[mt][nt][2], acc[mt][nt][3]);
            }
            quad_transpose(lo, lane);
            quad_transpose(hi, lane);
            const int row = bblk + mt * 16 + (lane >> 2);
            const int col = cg * 256 + nj * 32 + (lane & 3) * 8;
            stg_cs_128(&g_marg[((size_t)row * MM + mode) * NN + col],
                       make_uint4(lo[0], lo[1], lo[2], lo[3]));
            stg_cs_128(&g_marg[((size_t)(row + 8) * MM + mode) * NN + col],
                       make_uint4(hi[0], hi[1], hi[2], hi[3]));
        }
    }
    #undef BOFF
}

// ---------------- kernel: chain via HMMA, state in D-fragments ----------------
// One warp = one batch; 16 warps/block; grid = B/16 = 2048.
#define CH_BUF 2560
#define C_SMEM (16 * 2 * CH_BUF)   // 81920

__global__ void __launch_bounds__(512, 2)
k_chain(float* __restrict__ out) {
    extern __shared__ unsigned char sm[];
    const int tid = threadIdx.x;
    const int wid = tid >> 5;
    const int lane = tid & 31;
    const int b = blockIdx.x * 16 + wid;

    unsigned char* buf = sm + wid * (2 * CH_BUF);
    const uint32_t abuf = smem_u32(buf);
    const char* gsrc = (const char*)(g_marg + (size_t)b * MM * NN);

    #pragma unroll
    for (int k = 0; k < 4; ++k) {
        int q = lane + 32 * k;
        cp_async16(abuf + (q >> 2) * 80 + (q & 3) * 16, gsrc + q * 16);
    }
    cp_commit();
    #pragma unroll
    for (int k = 0; k < 4; ++k) {
        int q = lane + 32 * k;
        cp_async16(abuf + CH_BUF + (q >> 2) * 80 + (q & 3) * 16, gsrc + 2048 + q * 16);
    }
    cp_commit();

    cp_wait<1>();
    __syncwarp();

    float D[2][4][4];
    {
        const int r0 = lane >> 2, c0 = 2 * (lane & 3);
        #pragma unroll
        for (int mt = 0; mt < 2; ++mt)
            #pragma unroll
            for (int nt = 0; nt < 4; ++nt) {
                int r = 16 * mt + r0, c = 8 * nt + c0;
                __nv_bfloat162 v0 =
                    *reinterpret_cast<__nv_bfloat162*>(buf + r * 80 + c * 2);
                __nv_bfloat162 v1 =
                    *reinterpret_cast<__nv_bfloat162*>(buf + (r + 8) * 80 + c * 2);
                float2 f0 = __bfloat1622float2(v0);
                float2 f1 = __bfloat1622float2(v1);
                D[mt][nt][0] = f0.x; D[mt][nt][1] = f0.y;
                D[mt][nt][2] = f1.x; D[mt][nt][3] = f1.y;
            }
    }

    const int i8 = lane & 7, tsel = lane >> 3;

    for (int m = 1; m < MM; ++m) {
        if (m < MM - 1) {
            uint32_t dst = abuf + ((m + 1) & 1) * CH_BUF;
            const char* src = gsrc + (size_t)(m + 1) * 2048;
            #pragma unroll
            for (int k = 0; k < 4; ++k) {
                int q = lane + 32 * k;
                cp_async16(dst + (q >> 2) * 80 + (q & 3) * 16, src + q * 16);
            }
            cp_commit();
            cp_wait<1>();
        } else {
            cp_wait<0>();
        }
        __syncwarp();

        const uint32_t mb = abuf + (m & 1) * CH_BUF;

        uint32_t B[2][4][2];
        #pragma unroll
        for (int ks = 0; ks < 2; ++ks)
            #pragma unroll
            for (int nh = 0; nh < 2; ++nh) {
                uint32_t addr = mb + (16 * ks + (tsel & 1) * 8 + i8) * 80 +
                                32 * nh + (tsel >> 1) * 16;
                uint32_t q0, q1, q2, q3;
                ldsm4_trans(q0, q1, q2, q3, addr);
                B[ks][2 * nh][0] = q0;     B[ks][2 * nh][1] = q1;
                B[ks][2 * nh + 1][0] = q2; B[ks][2 * nh + 1][1] = q3;
            }

        uint32_t A[2][2][4];
        #pragma unroll
        for (int mt = 0; mt < 2; ++mt)
            #pragma unroll
            for (int ks = 0; ks < 2; ++ks) {
                A[mt][ks][0] = bf2_bits(D[mt][2 * ks][0], D[mt][2 * ks][1]);
                A[mt][ks][1] = bf2_bits(D[mt][2 * ks][2], D[mt][2 * ks][3]);
                A[mt][ks][2] = bf2_bits(D[mt][2 * ks + 1][0], D[mt][2 * ks + 1][1]);
                A[mt][ks][3] = bf2_bits(D[mt][2 * ks + 1][2], D[mt][2 * ks + 1][3]);
            }

        #pragma unroll
        for (int mt = 0; mt < 2; ++mt)
            #pragma unroll
            for (int nt = 0; nt < 4; ++nt)
                #pragma unroll
                for (int e = 0; e < 4; ++e) D[mt][nt][e] = 0.0f;

        #pragma unroll
        for (int mt = 0; mt < 2; ++mt)
            #pragma unroll
            for (int nt = 0; nt < 4; ++nt)
                #pragma unroll
                for (int ks = 0; ks < 2; ++ks)
                    mma_bf16(D[mt][nt], A[mt][ks], B[ks][nt][0], B[ks][nt][1]);
    }

    {
        float tr = 0.0f;
        const int r0 = lane >> 2, c0 = 2 * (lane & 3);
        #pragma unroll
        for (int mt = 0; mt < 2; ++mt)
            #pragma unroll
            for (int nt = 0; nt < 4; ++nt) {
                int rA = 16 * mt + r0, rB = rA + 8, c = 8 * nt + c0;
                if (c == rA)     tr += D[mt][nt][0];
                if (c + 1 == rA) tr += D[mt][nt][1];
                if (c == rB)     tr += D[mt][nt][2];
                if (c + 1 == rB) tr += D[mt][nt][3];
            }
        #pragma unroll
        for (int o = 16; o > 0; o >>= 1) tr += __shfl_xor_sync(0xffffffffu, tr, o);
        if (lane == 0)
            out[b] = logf(fmaxf(tr, 1e-12f)) - g_lognorm;
    }
}

// ---------------- launch ----------------
extern "C" void kernel_launch(void* const* d_in, const int* in_sizes, int n_in,
                              void* d_out, int out_size) {
    const float* value     = (const float*)d_in[0];  // (B, M)
    const float* location  = (const float*)d_in[1];  // (D, M)
    const float* log_scale = (const float*)d_in[2];  // (D, M)
    const float* cores     = (const float*)d_in[3];  // (M, D, R, R)
    float* out = (float*)d_out;

    const int B = in_sizes[0] / MM;   // 32768

    k_prep<<<(MM * 4 * 8 * 16 * 2 * 32) / 256, 256>>>(cores);
    k_modesum<<<MM, 1024>>>(cores);
    k_normchain<<<1, 1024>>>();

    static bool attr_done = false;
    if (!attr_done) {
        cudaFuncSetAttribute(k_margins,
                             cudaFuncAttributeMaxDynamicSharedMemorySize, M_SMEM);
        cudaFuncSetAttribute(k_chain,
                             cudaFuncAttributeMaxDynamicSharedMemorySize, C_SMEM);
        attr_done = true;
    }

    k_margins<<<(B / MT) * MM, 256, M_SMEM>>>(value, location, log_scale);
    k_chain<<<B / 16, 512, C_SMEM>>>(out);
}